// round 17
// baseline (speedup 1.0000x reference)
#include <cuda_runtime.h>

// STTEncoder: replicate the reference's fp32 integral image bitwise.
// jnp.cumsum -> reduce_window -> XLA ReduceWindowRewriter(base=16):
// blocked-sequential recursive scan (PASS since R7, rel_err 1.6e-8).
// R14: stage12 chunk size 512->256px => smem 105->71KB => 3 blocks/SM
// (48 warps, latency-bound fix). stage3 tiles the 17x17 ii grid in smem
// (289 loads vs 2048). All rounding orders preserved op-for-op.

#define IMG_W 1280
#define TS 16
constexpr int NTOK = 172;
constexpr int N1 = IMG_W + 1;   // padded scan length (1281)
constexpr int NB1 = 81;         // ceil(1281/16)
constexpr int NB2 = 6;

struct Tok { int x, y, s; };
struct Table { Tok t[NTOK]; int count; };

constexpr Table make_table() {
    Table tb{};
    constexpr int STR[5] = {1, 2, 4, 6, 8};
    constexpr int GRD[5] = {4, 4, 6, 8, 10};
    int n = 0;
    int plo = 0, phi = 0;
    bool has = false;
    for (int sc = 0; sc < 5; ++sc) {
        int s = STR[sc], g = GRD[sc];
        int cov = g * TS * s;
        int off = (IMG_W - cov) / 2;
        for (int j = 0; j < g; ++j)
            for (int i = 0; i < g; ++i) {
                int x = off + i * TS * s;
                int y = off + j * TS * s;
                if (has && x >= plo && x + TS * s <= phi &&
                    y >= plo && y + TS * s <= phi)
                    continue;
                tb.t[n].x = x; tb.t[n].y = y; tb.t[n].s = s; ++n;
            }
        plo = off; phi = off + cov; has = true;
    }
    tb.count = n;
    return tb;
}
static_assert(make_table().count == NTOK, "token count mismatch");
__constant__ Table TOKS = make_table();

// ---- needed boundary coordinate set (same for x and y) ----
struct BMask { bool m[N1]; };
constexpr BMask make_bmask() {
    BMask b{};
    Table tb = make_table();
    for (int t = 0; t < NTOK; ++t) {
        int s = tb.t[t].s;
        for (int i = 0; i <= TS; ++i) {
            b.m[tb.t[t].x + s * i] = true;
            b.m[tb.t[t].y + s * i] = true;
        }
    }
    return b;
}
constexpr int count_bounds() {
    BMask b = make_bmask(); int c = 0;
    for (int i = 0; i < N1; ++i) if (b.m[i]) ++c;
    return c;
}
constexpr int NX = count_bounds();
static_assert(NX <= 512, "boundary set too large");
constexpr int NX32 = (NX + 31) / 32 * 32;
constexpr int NCG = NX32 / 32;

struct BMapT { short cmap[N1]; };
constexpr BMapT make_bmap() {
    BMapT r{};
    BMask b = make_bmask();
    int c = 0;
    for (int i = 0; i < N1; ++i) {
        if (b.m[i]) { r.cmap[i] = (short)c; ++c; }
        else r.cmap[i] = -1;
    }
    return r;
}
__device__ const BMapT BMAP = make_bmap();

// per-16-block needed-position mask + cumulative output base
struct BlkInfo { unsigned short mask; short base; };
struct BlkTab { BlkInfo b[NB1]; int total; };
constexpr BlkTab make_blk() {
    BlkTab t{};
    BMask m = make_bmask();
    int cnt = 0;
    for (int r = 0; r < NB1; ++r) {
        t.b[r].base = (short)cnt;
        unsigned short msk = 0;
        for (int j = 0; j < 16; ++j) {
            int i = r * 16 + j;
            if (i < N1 && m.m[i]) { msk |= (unsigned short)(1u << j); ++cnt; }
        }
        t.b[r].mask = msk;
    }
    t.total = cnt;
    return t;
}
static_assert(make_blk().total == NX, "mask/base table inconsistent");
__device__ const BlkTab BLK = make_blk();

// x/y-block index of each sampled coordinate
struct RTab { short r[NX]; };
constexpr RTab make_rtab() {
    RTab t{};
    BMask b = make_bmask();
    int c = 0;
    for (int i = 0; i < N1; ++i)
        if (b.m[i]) { t.r[c] = (short)(i >> 4); ++c; }
    return t;
}
__device__ const RTab RBLK = make_rtab();

// ---- scratch (device globals: no allocation allowed) ----
__device__ float g_P[48ull * NX * NX32];     // sampled level-1 y-prefixes
__device__ float g_B[48ull * NB1 * NX32];    // y block sums
__device__ float g_Add[48ull * NB1 * NX32];  // add[r][col]

// dynamic smem layout (words)
constexpr int CHW    = 288;                // padded words per 256px chunk
constexpr int SM_BUF = 16 * 2 * CHW;       // per-warp double-buffered chunks
constexpr int SM_XS  = 16 * NX32;          // sampled x-prefixes per row
constexpr int SM_BS  = 16 * 96;            // per-warp block sums (padded)
constexpr int SM_ADD = 16 * 84;            // per-warp add table
constexpr int SMEM_WORDS = SM_BUF + SM_XS + SM_BS + SM_ADD;

// ============ Fused stage 1+2a: one warp per row, warp-synchronous ==========
__global__ __launch_bounds__(512, 3) void stt_stage12(const float* __restrict__ img) {
    extern __shared__ __align__(16) float smem[];
    float* bufs = smem;
    float* xs   = smem + SM_BUF;
    float* bsA  = xs + SM_XS;
    float* adA  = bsA + SM_BS;

    const int r  = blockIdx.x;       // y-block
    const int bc = blockIdx.y;
    const int t  = threadIdx.x;
    const int w  = t >> 5, l = t & 31;

    float* buf_w  = bufs + w * (2 * CHW);
    float* xs_w   = xs + w * NX32;
    float* bsum_w = bsA + w * 96;
    float* sadd_w = adA + w * 84;

    const int yy = r * 16 + w - 1;   // padded row element index -> image row
    const bool valid = (yy >= 0) && (yy < IMG_W);

    if (valid) {
        const float* row = img + ((size_t)bc * IMG_W + yy) * IMG_W;

        auto issue_chunk = [&](int c) {          // c = 0..4, 64 float4 each
            const float4* s4 = reinterpret_cast<const float4*>(row) + 64 * c;
            float* db = buf_w + (c & 1) * CHW;
#pragma unroll
            for (int k = 0; k < 2; ++k) {
                const int j = l + 32 * k;
                unsigned sa = (unsigned)__cvta_generic_to_shared(
                    &db[4 * j + 4 * (j >> 3)]);
                asm volatile("cp.async.ca.shared.global [%0], [%1], 16;\n"
                             :: "r"(sa), "l"(s4 + j));
            }
            asm volatile("cp.async.commit_group;\n" ::: "memory");
        };

        issue_chunk(0);
        issue_chunk(1);

        float carry = 0.f;
        for (int c = 0; c < 5; ++c) {
            asm volatile("cp.async.wait_group 1;\n" ::: "memory");
            __syncwarp();
            const float* db = buf_w + (c & 1) * CHW;
            float4 a = make_float4(0.f, 0.f, 0.f, 0.f);
            float4 b = a, cv = a, d = a;
            if (l < 16) {
                const int W = 16 * l + 4 * (l >> 1);
                a  = *reinterpret_cast<const float4*>(&db[W]);
                b  = *reinterpret_cast<const float4*>(&db[W + 4]);
                cv = *reinterpret_cast<const float4*>(&db[W + 8]);
                d  = *reinterpret_cast<const float4*>(&db[W + 12]);
            }
            const float last = d.w;
            float e0 = __shfl_up_sync(0xffffffffu, last, 1);
            if (l == 0) e0 = carry;              // chunk boundary / global pad
            if (l < 16) {
                const int B = 16 * c + l;        // 0..79
                const BlkInfo bi = BLK.b[B];
                const unsigned m = bi.mask;
                int o = bi.base;
                float acc = 0.f + e0;            // exact: fold init 0 + elem0
                if (m & 1u) xs_w[o++] = acc;
                acc = acc + a.x;  if (m & (1u << 1))  xs_w[o++] = acc;
                acc = acc + a.y;  if (m & (1u << 2))  xs_w[o++] = acc;
                acc = acc + a.z;  if (m & (1u << 3))  xs_w[o++] = acc;
                acc = acc + a.w;  if (m & (1u << 4))  xs_w[o++] = acc;
                acc = acc + b.x;  if (m & (1u << 5))  xs_w[o++] = acc;
                acc = acc + b.y;  if (m & (1u << 6))  xs_w[o++] = acc;
                acc = acc + b.z;  if (m & (1u << 7))  xs_w[o++] = acc;
                acc = acc + b.w;  if (m & (1u << 8))  xs_w[o++] = acc;
                acc = acc + cv.x; if (m & (1u << 9))  xs_w[o++] = acc;
                acc = acc + cv.y; if (m & (1u << 10)) xs_w[o++] = acc;
                acc = acc + cv.z; if (m & (1u << 11)) xs_w[o++] = acc;
                acc = acc + cv.w; if (m & (1u << 12)) xs_w[o++] = acc;
                acc = acc + d.x;  if (m & (1u << 13)) xs_w[o++] = acc;
                acc = acc + d.y;  if (m & (1u << 14)) xs_w[o++] = acc;
                acc = acc + d.z;  if (m & (1u << 15)) xs_w[o++] = acc;
                bsum_w[B] = acc;
            }
            carry = __shfl_sync(0xffffffffu, last, 15);  // px 256c+255
            __syncwarp();                        // all LDS done -> buffer free
            if (c < 3) issue_chunk(c + 2);
            else asm volatile("cp.async.commit_group;\n" ::: "memory");
        }

        // block 80: element 1280 only (pixel 1279 = carry)
        if (l == 0) {
            const float acc = 0.f + carry;
            bsum_w[80] = acc;
            const BlkInfo bi = BLK.b[80];
            if (bi.mask & 1u) xs_w[bi.base] = acc;
        }
        if (l < 15) bsum_w[81 + l] = 0.f;        // padded block sums
        __syncwarp();

        // level 2: lanes 0..5, register fold of 16 block sums (in place)
        if (l < 6) {
            float* bs = bsum_w + l * 16;
            float4 A = *reinterpret_cast<const float4*>(bs);
            float4 Bv = *reinterpret_cast<const float4*>(bs + 4);
            float4 C = *reinterpret_cast<const float4*>(bs + 8);
            float4 D = *reinterpret_cast<const float4*>(bs + 12);
            float acc = 0.f;
            acc = acc + A.x;  A.x = acc;
            acc = acc + A.y;  A.y = acc;
            acc = acc + A.z;  A.z = acc;
            acc = acc + A.w;  A.w = acc;
            acc = acc + Bv.x; Bv.x = acc;
            acc = acc + Bv.y; Bv.y = acc;
            acc = acc + Bv.z; Bv.z = acc;
            acc = acc + Bv.w; Bv.w = acc;
            acc = acc + C.x;  C.x = acc;
            acc = acc + C.y;  C.y = acc;
            acc = acc + C.z;  C.z = acc;
            acc = acc + C.w;  C.w = acc;
            acc = acc + D.x;  D.x = acc;
            acc = acc + D.y;  D.y = acc;
            acc = acc + D.z;  D.z = acc;
            acc = acc + D.w;  D.w = acc;
            *reinterpret_cast<float4*>(bs)      = A;
            *reinterpret_cast<float4*>(bs + 4)  = Bv;
            *reinterpret_cast<float4*>(bs + 8)  = C;
            *reinterpret_cast<float4*>(bs + 12) = D;
        }
        __syncwarp();

        // level 3: lane 0, exclusive fold of group totals; broadcast
        float o1 = 0.f, o2 = 0.f, o3 = 0.f, o4 = 0.f, o5 = 0.f;
        if (l == 0) {
            float acc = 0.f;
            acc = acc + bsum_w[15]; o1 = acc;
            acc = acc + bsum_w[31]; o2 = acc;
            acc = acc + bsum_w[47]; o3 = acc;
            acc = acc + bsum_w[63]; o4 = acc;
            acc = acc + bsum_w[79]; o5 = acc;
        }
        o1 = __shfl_sync(0xffffffffu, o1, 0);
        o2 = __shfl_sync(0xffffffffu, o2, 0);
        o3 = __shfl_sync(0xffffffffu, o3, 0);
        o4 = __shfl_sync(0xffffffffu, o4, 0);
        o5 = __shfl_sync(0xffffffffu, o5, 0);

        // add[rr] = off2[(rr-1)>>4] + b2prefix[rr-1]
#pragma unroll
        for (int q = 0; q < 3; ++q) {
            const int rr = l + 32 * q;
            if (rr <= 80) {
                float v = 0.f;
                if (rr > 0) {
                    const int g = (rr - 1) >> 4;
                    const float off = (g == 0) ? 0.f : (g == 1) ? o1 :
                                      (g == 2) ? o2 : (g == 3) ? o3 :
                                      (g == 4) ? o4 : o5;
                    v = off + bsum_w[rr - 1];
                }
                sadd_w[rr] = v;
            }
        }
        __syncwarp();

        // transform xs in place: p -> S = (rr ? add[rr] + p : p)
        for (int i = l; i < NX; i += 32) {
            const int rr = RBLK.r[i];
            float v = xs_w[i];
            if (rr > 0) v = sadd_w[rr] + v;
            xs_w[i] = v;
        }
    } else {
        for (int i = l; i < NX; i += 32) xs_w[i] = 0.f;  // padded rows
    }
    __syncthreads();

    // ---- y level-1 fold over the 16 padded rows (exact fold order) ----
    if (t < NX) {
        const BlkInfo bi = BLK.b[r];
        float acc = 0.f;
        int o = bi.base;
        float* P = g_P + (size_t)bc * NX * NX32 + t;
        const float* x0 = xs + t;
#pragma unroll
        for (int j = 0; j < 16; ++j) {
            acc = acc + x0[j * NX32];
            if ((bi.mask >> j) & 1) { P[(size_t)o * NX32] = acc; ++o; }
        }
        g_B[((size_t)bc * NB1 + r) * NX32 + t] = acc;
    }
}

// ===== Stage 2b: exact level-2/3 combine over block sums (per column) =======
__global__ __launch_bounds__(32) void stt_stage2b() {
    const int col = blockIdx.x * 32 + threadIdx.x;
    const int bc  = blockIdx.y;
    const float* B = g_B   + (size_t)bc * NB1 * NX32 + col;
    float*       A = g_Add + (size_t)bc * NB1 * NX32 + col;

    float acc2 = 0.f;     // b2prefix[r-1] at block entry
    float off_cur = 0.f;  // off2[current group]
#pragma unroll 4
    for (int r = 0; r < NB1; ++r) {
        const float Bv = B[(size_t)r * NX32];
        const float off_used = off_cur;
        if (r > 0 && (r & 15) == 0)
            off_cur = off_cur + acc2;            // off2[u] = off2[u-1]+total[u-1]
        A[(size_t)r * NX32] = off_used + acc2;   // add[r] (r=0 slot unused)
        acc2 = ((r & 15) == 0) ? Bv : (acc2 + Bv);
    }
}

// ====== Stage 3: smem-tiled 17x17 ii grid + 4-corner diff + divide ==========
__global__ __launch_bounds__(256) void stt_stage3(float* __restrict__ out) {
    __shared__ float ii[17][18];
    const int tok = blockIdx.x;
    const int bc  = blockIdx.y;
    const Tok tk = TOKS.t[tok];
    const int t  = threadIdx.x;

    const float* P   = g_P   + (size_t)bc * NX * NX32;
    const float* Add = g_Add + (size_t)bc * NB1 * NX32;

    // cooperative load of the token's 17x17 sampled ii values
    for (int idx = t; idx < 289; idx += 256) {
        const int yi = idx / 17, xi = idx - yi * 17;
        const int cy = BMAP.cmap[tk.y + tk.s * yi];
        const int cx = BMAP.cmap[tk.x + tk.s * xi];
        float v = P[(size_t)cy * NX32 + cx];
        const int rr = RBLK.r[cy];
        if (rr > 0) v = Add[(size_t)rr * NX32 + cx] + v;   // exact final add
        ii[yi][xi] = v;
    }
    __syncthreads();

    const int tx = t & 15, ty = t >> 4;
    const float A = ii[ty + 1][tx + 1];
    const float B = ii[ty + 1][tx];
    const float C = ii[ty][tx + 1];
    const float D = ii[ty][tx];
    const float box = ((A - B) - C) + D;   // reference op order

    const int b = bc / 3, ch = bc % 3;
    const size_t o = ((((size_t)b * NTOK + tok) * 3 + ch) * TS + ty) * TS + tx;
    out[o] = box / (float)(tk.s * tk.s);
}

extern "C" void kernel_launch(void* const* d_in, const int* in_sizes, int n_in,
                              void* d_out, int out_size) {
    const float* img = (const float*)d_in[0];
    float* out = (float*)d_out;

    cudaFuncSetAttribute(stt_stage12,
                         cudaFuncAttributeMaxDynamicSharedMemorySize,
                         SMEM_WORDS * 4);

    dim3 g12(NB1, 48);
    stt_stage12<<<g12, 512, SMEM_WORDS * 4>>>(img);

    dim3 g2b(NCG, 48);
    stt_stage2b<<<g2b, 32>>>();

    dim3 g3(NTOK, 48);
    stt_stage3<<<g3, 256>>>(out);
}